// round 8
// baseline (speedup 1.0000x reference)
#include <cuda_runtime.h>

#define FEATURES 2048
#define SCALE 4.0f

// out = sigmoid(SCALE * (x * w[f] + b[f])), elementwise over [N, FEATURES] fp32.
// Pure HBM-streaming: float4 loads/stores, w/b broadcast from L1 (8 KB each).
__global__ void __launch_bounds__(256) onetoone_sigmoid_kernel(
    const float4* __restrict__ x,
    const float4* __restrict__ w,
    const float4* __restrict__ b,
    float4* __restrict__ out,
    int total4)
{
    int i = blockIdx.x * blockDim.x + threadIdx.x;
    if (i >= total4) return;

    // FEATURES/4 = 512 float4 per row; feature index for this vec4
    int fi = i & (FEATURES / 4 - 1);

    float4 xv = x[i];
    float4 wv = __ldg(&w[fi]);
    float4 bv = __ldg(&b[fi]);

    float4 r;
    {
        float z;
        z = SCALE * fmaf(xv.x, wv.x, bv.x);
        r.x = 1.0f / (1.0f + __expf(-z));
        z = SCALE * fmaf(xv.y, wv.y, bv.y);
        r.y = 1.0f / (1.0f + __expf(-z));
        z = SCALE * fmaf(xv.z, wv.z, bv.z);
        r.z = 1.0f / (1.0f + __expf(-z));
        z = SCALE * fmaf(xv.w, wv.w, bv.w);
        r.w = 1.0f / (1.0f + __expf(-z));
    }
    out[i] = r;
}

extern "C" void kernel_launch(void* const* d_in, const int* in_sizes, int n_in,
                              void* d_out, int out_size)
{
    const float4* x = (const float4*)d_in[0];   // input  [N, FEATURES] fp32
    const float4* w = (const float4*)d_in[1];   // weight [FEATURES]    fp32
    const float4* b = (const float4*)d_in[2];   // bias   [FEATURES]    fp32
    float4* out = (float4*)d_out;               // output [N, FEATURES] fp32

    int total4 = out_size / 4;                  // 32768*2048/4 = 16,777,216
    int threads = 256;
    int blocks = (total4 + threads - 1) / threads;
    onetoone_sigmoid_kernel<<<blocks, threads>>>(x, w, b, out, total4);
}

// round 9
// speedup vs baseline: 1.0804x; 1.0804x over previous
#include <cuda_runtime.h>

#define FEATURES 2048
#define SCALE 4.0f
#define UNROLL 4
#define TPB 256

// out = sigmoid(SCALE * (x * w[f] + b[f])) over [32768, 2048] fp32.
// HBM-bound streaming kernel. 4x thread coarsening: 4 independent LDG.128s
// front-batched per thread (MLP=4) to keep the L1tex queue deep without
// relying on occupancy. x/out use .cs (evict-first) hints -- zero reuse;
// w/b (8 KB each) stay L1-cached via __ldg.
__global__ void __launch_bounds__(TPB) onetoone_sigmoid_k4(
    const float4* __restrict__ x,
    const float4* __restrict__ w,
    const float4* __restrict__ b,
    float4* __restrict__ out,
    int total4)
{
    // Each block owns a contiguous chunk of UNROLL*TPB float4s.
    int base = blockIdx.x * (TPB * UNROLL) + threadIdx.x;

    int   idx[UNROLL];
    bool  ok[UNROLL];
    float4 xv[UNROLL];

    // Front-batched independent loads (ptxas will group these -> MLP_p1=4)
    #pragma unroll
    for (int u = 0; u < UNROLL; u++) {
        idx[u] = base + u * TPB;
        ok[u]  = idx[u] < total4;
        if (ok[u]) xv[u] = __ldcs(&x[idx[u]]);
    }

    #pragma unroll
    for (int u = 0; u < UNROLL; u++) {
        if (!ok[u]) continue;
        int fi = idx[u] & (FEATURES / 4 - 1);
        float4 wv = __ldg(&w[fi]);
        float4 bv = __ldg(&b[fi]);

        float4 r;
        float z;
        z = SCALE * fmaf(xv[u].x, wv.x, bv.x);
        r.x = 1.0f / (1.0f + __expf(-z));
        z = SCALE * fmaf(xv[u].y, wv.y, bv.y);
        r.y = 1.0f / (1.0f + __expf(-z));
        z = SCALE * fmaf(xv[u].z, wv.z, bv.z);
        r.z = 1.0f / (1.0f + __expf(-z));
        z = SCALE * fmaf(xv[u].w, wv.w, bv.w);
        r.w = 1.0f / (1.0f + __expf(-z));

        __stcs(&out[idx[u]], r);
    }
}

extern "C" void kernel_launch(void* const* d_in, const int* in_sizes, int n_in,
                              void* d_out, int out_size)
{
    const float4* x = (const float4*)d_in[0];   // input  [N, FEATURES] fp32
    const float4* w = (const float4*)d_in[1];   // weight [FEATURES]    fp32
    const float4* b = (const float4*)d_in[2];   // bias   [FEATURES]    fp32
    float4* out = (float4*)d_out;

    int total4 = out_size / 4;                  // 16,777,216
    int per_block = TPB * UNROLL;               // 1024 float4 per block
    int blocks = (total4 + per_block - 1) / per_block;  // 16384
    onetoone_sigmoid_k4<<<blocks, TPB>>>(x, w, b, out, total4);
}

// round 10
// speedup vs baseline: 1.0858x; 1.0051x over previous
#include <cuda_runtime.h>

#define FEATURES   2048
#define SCALE      4.0f
#define TPB        256
#define UNROLL     8
#define PER_BLOCK  (TPB * UNROLL)   // 2048 float4 = 4 rows of FEATURES

// out = sigmoid(SCALE * (x * w[f] + b[f])) over [32768, 2048] fp32. HBM-bound.
//
// Exact-cover fast path: PER_BLOCK (2048) is a multiple of FEATURES/4 (512),
// so fi = idx & 511 depends only on (tid, u&1): fi = tid + (u&1)*256.
// => hoist w/b to 2 register-resident float4 pairs, SCALE pre-folded.
// 8 independent front-batched LDG.128 per thread (MLP=8) hide DRAM latency
// without relying on occupancy. x/out streamed with .cs (evict-first).
__global__ void __launch_bounds__(TPB) onetoone_sigmoid_k8_exact(
    const float4* __restrict__ x,
    const float4* __restrict__ w,
    const float4* __restrict__ b,
    float4* __restrict__ out)
{
    const int tid  = threadIdx.x;
    const int base = blockIdx.x * PER_BLOCK + tid;

    // Two distinct (w,b) pairs per thread; fold SCALE in once.
    float4 w0 = __ldg(&w[tid]);
    float4 b0 = __ldg(&b[tid]);
    float4 w1 = __ldg(&w[tid + TPB]);
    float4 b1 = __ldg(&b[tid + TPB]);
    w0.x *= SCALE; w0.y *= SCALE; w0.z *= SCALE; w0.w *= SCALE;
    b0.x *= SCALE; b0.y *= SCALE; b0.z *= SCALE; b0.w *= SCALE;
    w1.x *= SCALE; w1.y *= SCALE; w1.z *= SCALE; w1.w *= SCALE;
    b1.x *= SCALE; b1.y *= SCALE; b1.z *= SCALE; b1.w *= SCALE;

    // Front-batched independent loads (MLP_p1 = 8).
    float4 xv[UNROLL];
    #pragma unroll
    for (int u = 0; u < UNROLL; u++)
        xv[u] = __ldcs(&x[base + u * TPB]);

    #pragma unroll
    for (int u = 0; u < UNROLL; u++) {
        const float4 wv = (u & 1) ? w1 : w0;
        const float4 bv = (u & 1) ? b1 : b0;
        float4 r;
        float z;
        z = fmaf(xv[u].x, wv.x, bv.x);  r.x = 1.0f / (1.0f + __expf(-z));
        z = fmaf(xv[u].y, wv.y, bv.y);  r.y = 1.0f / (1.0f + __expf(-z));
        z = fmaf(xv[u].z, wv.z, bv.z);  r.z = 1.0f / (1.0f + __expf(-z));
        z = fmaf(xv[u].w, wv.w, bv.w);  r.w = 1.0f / (1.0f + __expf(-z));
        __stcs(&out[base + u * TPB], r);
    }
}

// Generic guarded fallback (only used if sizes ever change).
__global__ void __launch_bounds__(TPB) onetoone_sigmoid_generic(
    const float4* __restrict__ x,
    const float4* __restrict__ w,
    const float4* __restrict__ b,
    float4* __restrict__ out,
    int total4)
{
    int i = blockIdx.x * blockDim.x + threadIdx.x;
    if (i >= total4) return;
    int fi = i & (FEATURES / 4 - 1);
    float4 xv = __ldcs(&x[i]);
    float4 wv = __ldg(&w[fi]);
    float4 bv = __ldg(&b[fi]);
    float4 r;
    float z;
    z = SCALE * fmaf(xv.x, wv.x, bv.x);  r.x = 1.0f / (1.0f + __expf(-z));
    z = SCALE * fmaf(xv.y, wv.y, bv.y);  r.y = 1.0f / (1.0f + __expf(-z));
    z = SCALE * fmaf(xv.z, wv.z, bv.z);  r.z = 1.0f / (1.0f + __expf(-z));
    z = SCALE * fmaf(xv.w, wv.w, bv.w);  r.w = 1.0f / (1.0f + __expf(-z));
    __stcs(&out[i], r);
}

extern "C" void kernel_launch(void* const* d_in, const int* in_sizes, int n_in,
                              void* d_out, int out_size)
{
    const float4* x = (const float4*)d_in[0];   // input  [N, FEATURES] fp32
    const float4* w = (const float4*)d_in[1];   // weight [FEATURES]    fp32
    const float4* b = (const float4*)d_in[2];   // bias   [FEATURES]    fp32
    float4* out = (float4*)d_out;

    int total4 = out_size / 4;                  // 16,777,216
    if ((total4 % PER_BLOCK) == 0) {
        int blocks = total4 / PER_BLOCK;        // 8192
        onetoone_sigmoid_k8_exact<<<blocks, TPB>>>(x, w, b, out);
    } else {
        int blocks = (total4 + TPB - 1) / TPB;
        onetoone_sigmoid_generic<<<blocks, TPB>>>(x, w, b, out, total4);
    }
}